// round 4
// baseline (speedup 1.0000x reference)
#include <cuda_runtime.h>
#include <math.h>

#define BN 16
#define HH 480
#define WW 640
#define HW (HH * WW)
#define HW4 (HW / 4)            // 76800 float4 per plane
#define GX 50
#define TPB 256
#define NBLK (GX * BN)          // 800 blocks
#define STRIDE4 (GX * TPB)      // 12800 float4 stride
#define ITERS (HW4 / STRIDE4)   // exactly 6
#define W4 (WW / 4)             // 160 float4 per row
#define ROWS_PER_ITER (STRIDE4 / W4) // 80

// Allocation-free scratch.
__device__ float g_partials[NBLK];
__device__ unsigned int g_count = 0;

// Exact GELU with fast path: for |z| >= 16, z*Phi(z) == max(z,0) to <1e-50 abs.
__device__ __forceinline__ float gelu_exact(float z) {
    float val = fmaxf(z, 0.0f);
    if (fabsf(z) < 16.0f) val = z * normcdff(z);
    return val;
}

__global__ __launch_bounds__(TPB, 5) void cheirality_fused(
    const float* __restrict__ pose,
    const float* __restrict__ grad,
    const float* __restrict__ nf,
    float* __restrict__ out)
{
    const int b   = blockIdx.y;
    const int tid = threadIdx.x;

    const float V0 = __ldg(pose + b * 6 + 0);
    const float V1 = __ldg(pose + b * 6 + 1);
    const float V2 = __ldg(pose + b * 6 + 2);
    const float O0 = __ldg(pose + b * 6 + 3);
    const float O1 = __ldg(pose + b * 6 + 4);
    const float O2 = __ldg(pose + b * 6 + 5);

    const float4* __restrict__ g0p = (const float4*)(grad + (size_t)b * 2 * HW);
    const float4* __restrict__ g1p = g0p + HW4;
    const float4* __restrict__ n0p = (const float4*)(nf + (size_t)b * 2 * HW);
    const float4* __restrict__ n1p = n0p + HW4;

    // Stride is a whole number of rows (80), so the column is loop-invariant.
    const int i0 = blockIdx.x * TPB + tid;
    const int h0 = i0 / W4;                    // const divisor -> mul/shift
    const float x0 = (float)((i0 - h0 * W4) * 4);

    float acc = 0.0f;

    #pragma unroll
    for (int kk = 0; kk < ITERS / 2; kk++) {
        const int ia = i0 + (2 * kk) * STRIDE4;
        const int ib = ia + STRIDE4;

        // ---- batch all 8 streaming loads up front (MLP = 8) ----
        float4 g0a = __ldcs(g0p + ia);
        float4 g1a = __ldcs(g1p + ia);
        float4 n0a = __ldcs(n0p + ia);
        float4 n1a = __ldcs(n1p + ia);
        float4 g0b = __ldcs(g0p + ib);
        float4 g1b = __ldcs(g1p + ib);
        float4 n0b = __ldcs(n0p + ib);
        float4 n1b = __ldcs(n1p + ib);

        #pragma unroll
        for (int half = 0; half < 2; half++) {
            const float4& g0 = half ? g0b : g0a;
            const float4& g1 = half ? g1b : g1a;
            const float4& n0 = half ? n0b : n0a;
            const float4& n1 = half ? n1b : n1a;

            const float y      = (float)(h0 + (2 * kk + half) * ROWS_PER_ITER);
            const float AV1    = fmaf(y, V2, -V1);        // -V1 + y*V2
            const float yO2    = y * O2;
            const float y2p1O0 = fmaf(y, y, 1.0f) * O0;   // (y^2+1)*O0
            const float yO0    = y * O0;
            const float yO1    = y * O1;

            const float* ga = &g0.x;
            const float* gb = &g1.x;
            const float* na = &n0.x;
            const float* nb = &n1.x;

            #pragma unroll
            for (int j = 0; j < 4; j++) {
                const float x = x0 + (float)j;

                const float AV0 = fmaf(x, V2, -V0);
                // BW0 = x*(y*O0) - (x^2+1)*O1 + y*O2
                const float BW0 = fmaf(x, yO0, fmaf(-fmaf(x, x, 1.0f), O1, yO2));
                // BW1 = (y^2+1)*O0 - x*(y*O1) - x*O2
                const float BW1 = fmaf(-x, yO1, fmaf(-x, O2, y2p1O0));

                const float gg0 = ga[j], gg1 = gb[j];
                const float s = fmaf(gg0, AV0, gg1 * AV1);
                const float t = (na[j] + nb[j]) - fmaf(gg0, BW0, gg1 * BW1);
                acc += gelu_exact(-(s * t));
            }
        }
    }

    // ---- block reduction (float tree) ----
    __shared__ float warp_sums[TPB / 32];
    __shared__ bool  is_last;
    const unsigned mask = 0xFFFFFFFFu;
    #pragma unroll
    for (int off = 16; off > 0; off >>= 1)
        acc += __shfl_down_sync(mask, acc, off);

    const int lane = tid & 31;
    const int wid  = tid >> 5;
    if (lane == 0) warp_sums[wid] = acc;
    __syncthreads();

    if (tid == 0) {
        float bsum = 0.0f;
        #pragma unroll
        for (int w = 0; w < TPB / 32; w++) bsum += warp_sums[w];
        g_partials[blockIdx.y * GX + blockIdx.x] = bsum;
        __threadfence();
        unsigned int old = atomicAdd(&g_count, 1u);
        is_last = (old == (unsigned)(NBLK - 1));
    }
    __syncthreads();

    // ---- last block: sum partials in double, write scalar ----
    if (is_last) {
        double v = 0.0;
        for (int i = tid; i < NBLK; i += TPB)
            v += (double)g_partials[i];

        __shared__ double dsums[TPB / 32];
        #pragma unroll
        for (int off = 16; off > 0; off >>= 1)
            v += __shfl_down_sync(mask, v, off);
        if (lane == 0) dsums[wid] = v;
        __syncthreads();

        if (tid == 0) {
            double total = 0.0;
            #pragma unroll
            for (int w = 0; w < TPB / 32; w++) total += dsums[w];
            out[0] = (float)(total / (double)((long long)BN * HW));
            g_count = 0;   // reset for next graph replay
        }
    }
}

extern "C" void kernel_launch(void* const* d_in, const int* in_sizes, int n_in,
                              void* d_out, int out_size) {
    const float* pose = (const float*)d_in[0];
    const float* grad = (const float*)d_in[1];
    const float* nf   = (const float*)d_in[2];
    float* out = (float*)d_out;

    dim3 grid(GX, BN);
    cheirality_fused<<<grid, TPB>>>(pose, grad, nf, out);
}

// round 5
// speedup vs baseline: 1.2737x; 1.2737x over previous
#include <cuda_runtime.h>
#include <math.h>

#define BN 16
#define HH 480
#define WW 640
#define HW (HH * WW)
#define HW4 (HW / 4)            // 76800 float4 per plane
#define GX 37
#define TPB 256
#define NBLK (GX * BN)          // 592 = 148 SMs * 4 CTAs exactly
#define STRIDE4 (GX * TPB)      // 9472
#define W4 (WW / 4)             // 160 float4 per row

// Allocation-free scratch.
__device__ float g_partials[NBLK];
__device__ unsigned int g_count = 0;

// Exact GELU, fast path: for |z| >= 16, z*Phi(z) == max(z,0) to <1e-50 abs.
__device__ __forceinline__ float gelu_exact(float z) {
    float val = fmaxf(z, 0.0f);
    if (fabsf(z) < 16.0f) val = z * normcdff(z);
    return val;
}

__device__ __forceinline__ float tile_sum(
    float4 g0, float4 g1, float4 n0, float4 n1, int i,
    float V0, float V1, float V2, float O0, float O1, float O2)
{
    const int   h  = i / W4;                 // const divisor -> mul/shift
    const float x0 = (float)((i - h * W4) * 4);
    const float y  = (float)h;

    const float AV1    = fmaf(y, V2, -V1);          // -V1 + y*V2
    const float yO2    = y * O2;
    const float y2p1O0 = fmaf(y, y, 1.0f) * O0;     // (y^2+1)*O0
    const float yO0    = y * O0;
    const float yO1    = y * O1;

    const float* ga = &g0.x;
    const float* gb = &g1.x;
    const float* na = &n0.x;
    const float* nb = &n1.x;

    float s4 = 0.0f;
    #pragma unroll
    for (int j = 0; j < 4; j++) {
        const float x = x0 + (float)j;

        const float AV0 = fmaf(x, V2, -V0);                        // -V0 + x*V2
        // BW0 = x*(y*O0) - (x^2+1)*O1 + y*O2
        const float BW0 = fmaf(x, yO0, fmaf(-fmaf(x, x, 1.0f), O1, yO2));
        // BW1 = (y^2+1)*O0 - x*(y*O1) - x*O2
        const float BW1 = fmaf(-x, yO1, fmaf(-x, O2, y2p1O0));

        const float gg0 = ga[j], gg1 = gb[j];
        const float s = fmaf(gg0, AV0, gg1 * AV1);
        const float t = (na[j] + nb[j]) - fmaf(gg0, BW0, gg1 * BW1);
        s4 += gelu_exact(-(s * t));
    }
    return s4;
}

__global__ __launch_bounds__(TPB, 4) void cheirality_fused(
    const float* __restrict__ pose,
    const float* __restrict__ grad,
    const float* __restrict__ nf,
    float* __restrict__ out)
{
    const int b   = blockIdx.y;
    const int tid = threadIdx.x;

    const float V0 = __ldg(pose + b * 6 + 0);
    const float V1 = __ldg(pose + b * 6 + 1);
    const float V2 = __ldg(pose + b * 6 + 2);
    const float O0 = __ldg(pose + b * 6 + 3);
    const float O1 = __ldg(pose + b * 6 + 4);
    const float O2 = __ldg(pose + b * 6 + 5);

    const float4* __restrict__ g0p = (const float4*)(grad + (size_t)b * 2 * HW);
    const float4* __restrict__ g1p = g0p + HW4;
    const float4* __restrict__ n0p = (const float4*)(nf + (size_t)b * 2 * HW);
    const float4* __restrict__ n1p = n0p + HW4;

    const int i0 = blockIdx.x * TPB + tid;   // < 9472, so every thread iterates

    float acc = 0.0f;

    // Software-pipelined grid-stride loop: issue next iteration's loads
    // before computing the current one (64-reg budget allows 8 in flight).
    int i = i0;
    float4 g0 = g0p[i], g1 = g1p[i], n0 = n0p[i], n1 = n1p[i];

    for (int inext = i + STRIDE4; inext < HW4; inext += STRIDE4) {
        float4 g0n = g0p[inext];
        float4 g1n = g1p[inext];
        float4 n0n = n0p[inext];
        float4 n1n = n1p[inext];

        acc += tile_sum(g0, g1, n0, n1, i, V0, V1, V2, O0, O1, O2);

        i = inext;
        g0 = g0n; g1 = g1n; n0 = n0n; n1 = n1n;
    }
    acc += tile_sum(g0, g1, n0, n1, i, V0, V1, V2, O0, O1, O2);

    // ---- block reduction (float tree) ----
    __shared__ float warp_sums[TPB / 32];
    __shared__ bool  is_last;
    const unsigned mask = 0xFFFFFFFFu;
    #pragma unroll
    for (int off = 16; off > 0; off >>= 1)
        acc += __shfl_down_sync(mask, acc, off);

    const int lane = tid & 31;
    const int wid  = tid >> 5;
    if (lane == 0) warp_sums[wid] = acc;
    __syncthreads();

    if (tid == 0) {
        float bsum = 0.0f;
        #pragma unroll
        for (int w = 0; w < TPB / 32; w++) bsum += warp_sums[w];
        g_partials[blockIdx.y * GX + blockIdx.x] = bsum;
        __threadfence();
        unsigned int old = atomicAdd(&g_count, 1u);
        is_last = (old == (unsigned)(NBLK - 1));
    }
    __syncthreads();

    // ---- last block: sum partials in double, write scalar ----
    if (is_last) {
        double v = 0.0;
        for (int p = tid; p < NBLK; p += TPB)
            v += (double)g_partials[p];

        __shared__ double dsums[TPB / 32];
        #pragma unroll
        for (int off = 16; off > 0; off >>= 1)
            v += __shfl_down_sync(mask, v, off);
        if (lane == 0) dsums[wid] = v;
        __syncthreads();

        if (tid == 0) {
            double total = 0.0;
            #pragma unroll
            for (int w = 0; w < TPB / 32; w++) total += dsums[w];
            out[0] = (float)(total / (double)((long long)BN * HW));
            g_count = 0;   // reset for next graph replay
        }
    }
}

extern "C" void kernel_launch(void* const* d_in, const int* in_sizes, int n_in,
                              void* d_out, int out_size) {
    const float* pose = (const float*)d_in[0];
    const float* grad = (const float*)d_in[1];
    const float* nf   = (const float*)d_in[2];
    float* out = (float*)d_out;

    dim3 grid(GX, BN);
    cheirality_fused<<<grid, TPB>>>(pose, grad, nf, out);
}